// round 14
// baseline (speedup 1.0000x reference)
#include <cuda_runtime.h>
#include <math.h>
#include <cstddef>

#define E_    50000
#define EPAD_ 50176               // 49 * 1024
#define N_    1000000
#define B_    8
#define L_    3
#define T_    3
#define NREL_ 401
#define R_    200
#define H_    256
#define G_    1024
#define TOPK_ 1000
#define BL_   24
#define CAP_  64
#define FRCAP 2048
#define LSTM_BLKS  96
#define BUILD_BLKS 489            // ceil(250000/512)
#define HTPB 1024

// ---------------- zeroed-every-launch block (single memset) ----------------
struct Zs {
    int cnt_h[E_];
    int cnt_t[E_];
    int spill;
};
__device__ Zs gZ;

// ---------------- persistent scratch ----------------
__device__ unsigned g_ell_h[(size_t)E_ * CAP_];   // tail | (rel<<16)
__device__ unsigned g_ell_t[(size_t)E_ * CAP_];   // head | (rel<<16)
__device__ int      g_sp_ent[2 * N_];
__device__ unsigned g_sp_pay[2 * N_];             // tgt | (rel<<16) | (dir<<31)
__device__ int      g_fr_ovf_e[(size_t)BL_ * E_]; // frontier overflow (ties beyond FRCAP)
__device__ float    g_fr_ovf_v[(size_t)BL_ * E_];
// lstm
__device__ float    g_preq[6 * B_ * G_], g_pree[6 * B_ * G_], g_gates[6 * B_ * G_];
__device__ float    g_hst[6 * B_ * H_], g_cst[6 * B_ * H_];
__device__ float    g_hseq[24 * B_ * H_];
__device__ float    g_logits[T_ * BL_ * NREL_], g_w[T_ * BL_ * NREL_];

__device__ unsigned g_bar_cnt = 0;
__device__ volatile unsigned g_bar_gen = 0;

__device__ __forceinline__ float sigm(float x) { return 1.f / (1.f + expf(-x)); }

// sub-grid barrier over exactly LSTM_BLKS blocks (build blocks never touch it;
// they always retire, so all LSTM blocks become co-resident -> no deadlock)
__device__ __forceinline__ void gridbar96() {
    __threadfence();
    __syncthreads();
    if (threadIdx.x == 0) {
        unsigned gen = g_bar_gen;
        if (atomicAdd(&g_bar_cnt, 1u) == LSTM_BLKS - 1) {
            g_bar_cnt = 0;
            __threadfence();
            g_bar_gen = gen + 1;
        } else {
            while (g_bar_gen == gen) __nanosleep(128);
        }
    }
    __syncthreads();
}

// ---------------- combined: BiLSTM (blocks 0..95) + ELL build (blocks 96..584) ----------------
__global__ void __launch_bounds__(512)
combo_kernel(const int4* __restrict__ h4, const int4* __restrict__ t4,
             const int4* __restrict__ r4, const int4* __restrict__ t24,
             const int* __restrict__ input_r, const float* __restrict__ emb,
             const float* __restrict__ Wihf, const float* __restrict__ Whhf,
             const float* __restrict__ bihf, const float* __restrict__ bhhf,
             const float* __restrict__ Wihb, const float* __restrict__ Whhb,
             const float* __restrict__ bihb, const float* __restrict__ bhhb,
             const float* __restrict__ linW, const float* __restrict__ linb) {
    const int tid = threadIdx.x;

    if (blockIdx.x >= LSTM_BLKS) {
        // ================= ELL build (spill-exact) =================
        int i = (blockIdx.x - LSTM_BLKS) * 512 + tid;
        if (i >= N_ / 4) return;
        int4 h = h4[i], t = t4[i], r = r4[i], t2 = t24[i];
#define DO1(hx, tx, rx, t2x) { \
        int pos = atomicAdd(&gZ.cnt_h[hx], 1); \
        unsigned pay = (unsigned)(tx) | ((unsigned)(rx) << 16); \
        if (pos < CAP_) g_ell_h[(size_t)(hx) * CAP_ + pos] = pay; \
        else { int sp = atomicAdd(&gZ.spill, 1); g_sp_ent[sp] = (hx); g_sp_pay[sp] = pay; } \
        int pos2 = atomicAdd(&gZ.cnt_t[t2x], 1); \
        unsigned pay2 = (unsigned)(hx) | ((unsigned)(rx) << 16); \
        if (pos2 < CAP_) g_ell_t[(size_t)(t2x) * CAP_ + pos2] = pay2; \
        else { int sp = atomicAdd(&gZ.spill, 1); g_sp_ent[sp] = (t2x); g_sp_pay[sp] = pay2 | 0x80000000u; } }
        DO1(h.x, t.x, r.x, t2.x); DO1(h.y, t.y, r.y, t2.y);
        DO1(h.z, t.z, r.z, t2.z); DO1(h.w, t.w, r.w, t2.w);
#undef DO1
        return;
    }

    // ================= BiLSTM + logits + softmax =================
    const int bid = blockIdx.x;                    // 0..95
    const int gid = bid * 512 + tid;
    __shared__ float s_buf[416];
    __shared__ float s_red[512];

    // --- pre: input projections for q and emb[-1] ---
    {
        int p = gid & 7, row = gid >> 3;           // 49152 threads exactly
        int ld = row >> 10, j = row & 1023;
        int dir = ld / 3, l = ld - dir * 3;
        const float4* w4 = (const float4*)((dir ? Wihb : Wihf) + ((size_t)(l * G_ + j)) * H_) + p * 8;
        const float4* e4 = (const float4*)(emb + (size_t)(NREL_ - 1) * H_) + p * 8;
        const float4* q4[B_];
        float aq[B_];
#pragma unroll
        for (int b = 0; b < B_; ++b) {
            q4[b] = (const float4*)(emb + (size_t)input_r[b] * H_) + p * 8;
            aq[b] = 0.f;
        }
        float ae = 0.f;
#pragma unroll
        for (int k = 0; k < 8; ++k) {
            float4 w = w4[k], e = e4[k];
            ae += w.x * e.x + w.y * e.y + w.z * e.z + w.w * e.w;
#pragma unroll
            for (int b = 0; b < B_; ++b) {
                float4 q = q4[b][k];
                aq[b] += w.x * q.x + w.y * q.y + w.z * q.z + w.w * q.w;
            }
        }
#pragma unroll
        for (int o = 1; o <= 4; o <<= 1) {
            ae += __shfl_xor_sync(0xffffffffu, ae, o);
#pragma unroll
            for (int b = 0; b < B_; ++b) aq[b] += __shfl_xor_sync(0xffffffffu, aq[b], o);
        }
        if (p == 0) {
            float bias = (dir ? bihb : bihf)[l * G_ + j] + (dir ? bhhb : bhhf)[l * G_ + j];
#pragma unroll
            for (int b = 0; b < B_; ++b) {
                int idx = (ld * 8 + b) * G_ + j;
                g_preq[idx] = aq[b] + bias;
                g_pree[idx] = ae + bias;
            }
        }
    }
    gridbar96();

    // --- 4 recurrence steps ---
    for (int s = 0; s < 4; ++s) {
        if (s > 0) {
            int p = gid & 7, row = gid >> 3;
            int ld = row >> 10, j = row & 1023;
            int dir = ld / 3, l = ld - dir * 3;
            const float4* w4 = (const float4*)((dir ? Whhb : Whhf) + ((size_t)(l * G_ + j)) * H_) + p * 8;
            const float4* hb = (const float4*)g_hst + (ld * 8) * 64 + p * 8;
            float acc[B_];
#pragma unroll
            for (int b = 0; b < B_; ++b) acc[b] = 0.f;
#pragma unroll
            for (int k = 0; k < 8; ++k) {
                float4 w = w4[k];
#pragma unroll
                for (int b = 0; b < B_; ++b) {
                    float4 h = hb[b * 64 + k];
                    acc[b] += w.x * h.x + w.y * h.y + w.z * h.z + w.w * h.w;
                }
            }
#pragma unroll
            for (int o = 1; o <= 4; o <<= 1)
#pragma unroll
                for (int b = 0; b < B_; ++b) acc[b] += __shfl_xor_sync(0xffffffffu, acc[b], o);
            if (p == 0) {
                const float* pre = ((dir == 0) && (s == 3)) ? g_pree : g_preq;
#pragma unroll
                for (int b = 0; b < B_; ++b) {
                    int idx = (ld * 8 + b) * G_ + j;
                    g_gates[idx] = pre[idx] + acc[b];
                }
            }
            gridbar96();
        }
        if (gid < 6 * B_ * H_) {
            int idx = gid;
            int ld = idx >> 11;
            int b  = (idx >> 8) & 7;
            int u  = idx & 255;
            int base2 = (ld * 8 + b) * G_;
            float gi, gf, gg, go, cprev;
            if (s == 0) {
                const float* src = (ld >= 3) ? g_pree : g_preq;   // bwd step0 sees emb[-1]
                gi = src[base2 + u]; gf = src[base2 + 256 + u];
                gg = src[base2 + 512 + u]; go = src[base2 + 768 + u];
                cprev = 0.f;
            } else {
                gi = g_gates[base2 + u]; gf = g_gates[base2 + 256 + u];
                gg = g_gates[base2 + 512 + u]; go = g_gates[base2 + 768 + u];
                cprev = g_cst[idx];
            }
            float c = sigm(gf) * cprev + sigm(gi) * tanhf(gg);
            float h = sigm(go) * tanhf(c);
            g_cst[idx] = c;
            g_hst[idx] = h;
            g_hseq[((ld * 4 + s) * 8 + b) * H_ + u] = h;
        }
        gridbar96();
    }

    // --- logits ---
    {
        const int TOTAL = NREL_ * 9 * 8;   // 28872
        int g = (gid < TOTAL) ? gid : (TOTAL - 1);
        int n = g / 72;
        int rem = g % 72;
        int tl = rem >> 3;
        int p = g & 7;
        int t = tl / 3, l = tl - t * 3;
        const float4* w1 = (const float4*)(linW + (size_t)n * 2 * H_) + p * 8;
        const float4* w2 = w1 + 64;
        const float4* hf = (const float4*)g_hseq + ((l * 4 + t) * 8) * 64 + p * 8;
        const float4* hb = (const float4*)g_hseq + (((3 + l) * 4 + (3 - t)) * 8) * 64 + p * 8;
        float acc[B_];
#pragma unroll
        for (int b = 0; b < B_; ++b) acc[b] = 0.f;
#pragma unroll
        for (int k = 0; k < 8; ++k) {
            float4 wa = w1[k], wb = w2[k];
#pragma unroll
            for (int b = 0; b < B_; ++b) {
                float4 a = hf[b * 64 + k];
                float4 c = hb[b * 64 + k];
                acc[b] += a.x * wa.x + a.y * wa.y + a.z * wa.z + a.w * wa.w
                        + c.x * wb.x + c.y * wb.y + c.z * wb.z + c.w * wb.w;
            }
        }
#pragma unroll
        for (int o = 1; o <= 4; o <<= 1)
#pragma unroll
            for (int b = 0; b < B_; ++b) acc[b] += __shfl_xor_sync(0xffffffffu, acc[b], o);
        if (gid < TOTAL && p == 0) {
            float bb = linb[n];
#pragma unroll
            for (int b = 0; b < B_; ++b)
                g_logits[(t * BL_ + b * 3 + l) * NREL_ + n] = acc[b] + bb;
        }
    }
    gridbar96();

    // --- softmax (72 rows over first 72 lstm blocks) ---
    if (bid < T_ * BL_) {
        const float* lg = g_logits + bid * NREL_;
        float* wout = g_w + bid * NREL_;
        float lmax = -1e30f;
        for (int i = tid; i < NREL_; i += 512) {
            float v = lg[i] * 0.1f;
            s_buf[i] = v;
            lmax = fmaxf(lmax, v);
        }
        s_red[tid] = lmax; __syncthreads();
        for (int o = 256; o > 0; o >>= 1) { if (tid < o) s_red[tid] = fmaxf(s_red[tid], s_red[tid + o]); __syncthreads(); }
        float m = s_red[0];
        __syncthreads();
        float lsum = 0.f;
        for (int i = tid; i < NREL_; i += 512) {
            float ex = expf(s_buf[i] - m);
            s_buf[i] = ex;
            lsum += ex;
        }
        s_red[tid] = lsum; __syncthreads();
        for (int o = 256; o > 0; o >>= 1) { if (tid < o) s_red[tid] += s_red[tid + o]; __syncthreads(); }
        float inv = 1.f / s_red[0];
        for (int i = tid; i < NREL_; i += 512) wout[i] = s_buf[i] * inv;
    }
}

// ---------------- fused hops: one block per (b,l), dense state in SMEM ----------------
// Propagate: warp-per-frontier-entry (coalesced ELL row reads), atomics-only.
// Normalizer/nnz/threshold/compact: dense smem scans.
__global__ void __launch_bounds__(HTPB, 1)
hops_kernel(const int* __restrict__ input_x, float* __restrict__ out) {
    extern __shared__ float s_state[];              // E_ floats = 200 KB
    __shared__ float    s_wr[NREL_];
    __shared__ unsigned s_fre[FRCAP];
    __shared__ float    s_frv[FRCAP];
    __shared__ int      s_hist[256];
    __shared__ float    s_wred[32];
    __shared__ int      s_ired[32];
    __shared__ float    s_nrm;
    __shared__ int      s_frc, s_nnz;
    __shared__ unsigned shp, shm;
    __shared__ int      shk;

    const int bl = blockIdx.x, tid = threadIdx.x;
    const int lane = tid & 31, wid = tid >> 5;      // 32 warps
    const int sc = gZ.spill;

    // zero state
    float4* st4 = (float4*)s_state;
    for (int i = tid; i < E_ / 4; i += HTPB) st4[i] = make_float4(0.f, 0.f, 0.f, 0.f);
    if (tid == 0) {
        s_frc = 1;
        s_fre[0] = (unsigned)input_x[bl / 3];
        s_frv[0] = 1.f;
    }
    __syncthreads();

    float nrm_prev = 1.f;                           // t=0: x0 used unnormalized
    for (int t = 0; t < T_; ++t) {
        // stage softmaxed relation weights in smem
        for (int i = tid; i < NREL_; i += HTPB) s_wr[i] = g_w[(t * BL_ + bl) * NREL_ + i];
        __syncthreads();
        const float inv = 1.f / fmaxf(nrm_prev, 1e-7f);
        const int fcnt = s_frc;

        // ---------------- propagate: warp per frontier entry ----------------
        for (int ent = wid; ent < fcnt; ent += 32) {
            unsigned e; float fv;
            if (ent < FRCAP) { e = s_fre[ent]; fv = s_frv[ent]; }
            else { e = (unsigned)g_fr_ovf_e[(size_t)bl * E_ + ent]; fv = g_fr_ovf_v[(size_t)bl * E_ + ent]; }
            float v = fv * inv;
            if (lane == 0) atomicAdd(&s_state[e], s_wr[NREL_ - 1] * v);   // identity
            int ch = min(gZ.cnt_h[e], CAP_);
            const unsigned* row = g_ell_h + (size_t)e * CAP_;
            for (int i = lane; i < ch; i += 32) {
                unsigned pk = row[i];
                atomicAdd(&s_state[pk & 0xFFFFu], v * s_wr[pk >> 16]);
            }
            int ct = min(gZ.cnt_t[e], CAP_);
            row = g_ell_t + (size_t)e * CAP_;
            for (int i = lane; i < ct; i += 32) {
                unsigned pk = row[i];
                atomicAdd(&s_state[pk & 0xFFFFu], v * s_wr[(pk >> 16) + R_]);
            }
            if (sc) {
                for (int i = lane; i < sc; i += 32) {
                    if ((unsigned)g_sp_ent[i] == e) {
                        unsigned pk = g_sp_pay[i];
                        int widx = (int)((pk >> 16) & 0x7FFFu) + ((pk >> 31) ? R_ : 0);
                        atomicAdd(&s_state[pk & 0xFFFFu], v * s_wr[widx]);
                    }
                }
            }
        }
        __syncthreads();

        // ---------------- dense sum + nnz (normalizer = state sum) ----------------
        {
            float ssum = 0.f; int c = 0;
            for (int i = tid; i < E_; i += HTPB) {
                float v = s_state[i];
                ssum += v;
                c += (v > 0.f);
            }
#pragma unroll
            for (int o = 16; o > 0; o >>= 1) {
                ssum += __shfl_down_sync(0xffffffffu, ssum, o);
                c += __shfl_down_sync(0xffffffffu, c, o);
            }
            if (lane == 0) { s_wred[wid] = ssum; s_ired[wid] = c; }
            __syncthreads();
            if (wid == 0) {
                float a = s_wred[lane]; int b2 = s_ired[lane];
#pragma unroll
                for (int o = 16; o > 0; o >>= 1) {
                    a += __shfl_down_sync(0xffffffffu, a, o);
                    b2 += __shfl_down_sync(0xffffffffu, b2, o);
                }
                if (lane == 0) { s_nrm = a; s_nnz = b2; }
            }
            __syncthreads();
        }
        const float nrm_out = s_nrm;
        const int nnz = s_nnz;

        if (t == T_ - 1) {
            // output: out[b] += state/nrm (3 channels per b -> global atomics)
            float invo = 1.f / fmaxf(nrm_out, 1e-7f);
            float* ob = out + (size_t)(bl / 3) * E_;
            for (int i = tid; i < E_; i += HTPB) {
                float v = s_state[i];
                if (v != 0.f) atomicAdd(&ob[i], v * invo);
            }
        } else {
            // exact top-k threshold via radix select (only if nnz > k); values >= 0
            float th = 0.f;
            if (nnz > TOPK_) {
                if (tid == 0) { shp = 0u; shm = 0u; shk = TOPK_; }
                __syncthreads();
                for (int pass = 0; pass < 4; ++pass) {
                    int shift = 24 - 8 * pass;
                    if (tid < 256) s_hist[tid] = 0;
                    __syncthreads();
                    unsigned mask = shm, pref = shp;
                    for (int i = tid; i < EPAD_; i += HTPB) {
                        unsigned bits = 0u; bool ok = false;
                        if (i < E_) {
                            bits = __float_as_uint(s_state[i]);
                            ok = (bits != 0u) && ((bits & mask) == pref);
                        }
                        int bin = (bits >> shift) & 255;
                        unsigned act = __ballot_sync(0xffffffffu, ok);
                        if (ok) {
                            unsigned mm = __match_any_sync(act, bin);
                            if (lane == (int)(__ffs(mm) - 1)) atomicAdd(&s_hist[bin], __popc(mm));
                        }
                    }
                    __syncthreads();
                    if (tid == 0) {
                        int cum = 0, krem = shk, sel = 0, newk = krem;
                        for (int bn = 255; bn >= 0; --bn) {
                            int c = s_hist[bn];
                            if (cum + c >= krem) { sel = bn; newk = krem - cum; break; }
                            cum += c;
                        }
                        shp = pref | ((unsigned)sel << shift);
                        shm = mask | (0xFFu << shift);
                        shk = newk;
                    }
                    __syncthreads();
                }
                th = __uint_as_float(shp);
            }
            __syncthreads();
            if (tid == 0) s_frc = 0;
            __syncthreads();
            // dense compact (keep v >= th, v > 0) + zero state for next hop
            for (int i = tid; i < EPAD_; i += HTPB) {
                float v = 0.f; bool keep = false;
                if (i < E_) {
                    v = s_state[i];
                    keep = (v >= th) && (v > 0.f);
                }
                unsigned bm = __ballot_sync(0xffffffffu, keep);
                if (bm) {
                    int ldr = (int)(__ffs(bm) - 1), base;
                    if (lane == ldr) base = atomicAdd(&s_frc, __popc(bm));
                    base = __shfl_sync(0xffffffffu, base, ldr);
                    if (keep) {
                        int p = base + __popc(bm & ((1u << lane) - 1u));
                        if (p < FRCAP) { s_fre[p] = (unsigned)i; s_frv[p] = v; }
                        else { g_fr_ovf_e[(size_t)bl * E_ + p] = i; g_fr_ovf_v[(size_t)bl * E_ + p] = v; }
                    }
                }
                if (i < E_) s_state[i] = 0.f;
            }
            nrm_prev = nrm_out;
            __syncthreads();
        }
    }
}

// ---------------- launch (single stream, 4 linear nodes) ----------------
extern "C" void kernel_launch(void* const* d_in, const int* in_sizes, int n_in,
                              void* d_out, int out_size) {
    (void)in_sizes; (void)n_in; (void)out_size;
    const int*   input_x = (const int*)d_in[0];
    const int*   input_r = (const int*)d_in[1];
    const int*   e2      = (const int*)d_in[2];
    const int*   t2e     = (const int*)d_in[3];
    const int*   r2      = (const int*)d_in[4];
    const float* emb     = (const float*)d_in[5];

    static bool init = false;
    if (!init) {
        cudaFuncSetAttribute(hops_kernel, cudaFuncAttributeMaxDynamicSharedMemorySize, E_ * 4);
        init = true;
    }

    void* pZ;
    cudaGetSymbolAddress(&pZ, gZ);

    cudaMemsetAsync(pZ, 0, sizeof(Zs), 0);
    cudaMemsetAsync(d_out, 0, (size_t)B_ * E_ * sizeof(float), 0);

    // BiLSTM (96 blocks, placed first) + build (489 blocks), overlapped in one launch
    combo_kernel<<<LSTM_BLKS + BUILD_BLKS, 512>>>(
        (const int4*)e2, (const int4*)(t2e + N_), (const int4*)r2, (const int4*)(e2 + 2 * N_),
        input_r, emb,
        (const float*)d_in[6], (const float*)d_in[7], (const float*)d_in[8],
        (const float*)d_in[9], (const float*)d_in[10], (const float*)d_in[11],
        (const float*)d_in[12], (const float*)d_in[13], (const float*)d_in[14],
        (const float*)d_in[15]);

    // fused hops: all 3 propagation rounds + top-k + output, per-(b,l) block
    hops_kernel<<<BL_, HTPB, E_ * 4>>>(input_x, (float*)d_out);
}

// round 15
// speedup vs baseline: 1.1450x; 1.1450x over previous
#include <cuda_runtime.h>
#include <math.h>
#include <cstddef>

#define E_    50000
#define N_    1000000
#define B_    8
#define L_    3
#define T_    3
#define NREL_ 401
#define R_    200
#define H_    256
#define G_    1024
#define TOPK_ 1000
#define BL_   24
#define CAP_  64
#define FRCAP 2048
#define LSTM_BLKS  96
#define BUILD_BLKS 489            // ceil(250000/512)
#define HTPB 1024

// ---------------- zeroed-every-launch block (single memset) ----------------
struct Zs {
    int cnt_h[E_];
    int cnt_t[E_];
    int spill;
};
__device__ Zs gZ;

// ---------------- persistent scratch ----------------
__device__ unsigned g_ell_h[(size_t)E_ * CAP_];   // tail | (rel<<16)
__device__ unsigned g_ell_t[(size_t)E_ * CAP_];   // head | (rel<<16)
__device__ int      g_sp_ent[2 * N_];
__device__ unsigned g_sp_pay[2 * N_];             // tgt | (rel<<16) | (dir<<31)
__device__ int      g_cand[(size_t)BL_ * E_];     // per-bl candidate lists (t < T-1 only)
__device__ int      g_fr_ovf_e[(size_t)BL_ * E_]; // frontier overflow (ties beyond FRCAP)
__device__ float    g_fr_ovf_v[(size_t)BL_ * E_];
// lstm
__device__ float    g_preq[6 * B_ * G_], g_pree[6 * B_ * G_], g_gates[6 * B_ * G_];
__device__ float    g_hst[6 * B_ * H_], g_cst[6 * B_ * H_];
__device__ float    g_hseq[24 * B_ * H_];
__device__ float    g_logits[T_ * BL_ * NREL_], g_w[T_ * BL_ * NREL_];

__device__ unsigned g_bar_cnt = 0;
__device__ volatile unsigned g_bar_gen = 0;

__device__ __forceinline__ float sigm(float x) { return 1.f / (1.f + expf(-x)); }

// sub-grid barrier over exactly LSTM_BLKS blocks (build blocks never touch it;
// they always retire, so all LSTM blocks become co-resident -> no deadlock)
__device__ __forceinline__ void gridbar96() {
    __threadfence();
    __syncthreads();
    if (threadIdx.x == 0) {
        unsigned gen = g_bar_gen;
        if (atomicAdd(&g_bar_cnt, 1u) == LSTM_BLKS - 1) {
            g_bar_cnt = 0;
            __threadfence();
            g_bar_gen = gen + 1;
        } else {
            while (g_bar_gen == gen) __nanosleep(128);
        }
    }
    __syncthreads();
}

// ---------------- combined: BiLSTM (blocks 0..95) + ELL build (blocks 96..584) ----------------
__global__ void __launch_bounds__(512)
combo_kernel(const int4* __restrict__ h4, const int4* __restrict__ t4,
             const int4* __restrict__ r4, const int4* __restrict__ t24,
             const int* __restrict__ input_r, const float* __restrict__ emb,
             const float* __restrict__ Wihf, const float* __restrict__ Whhf,
             const float* __restrict__ bihf, const float* __restrict__ bhhf,
             const float* __restrict__ Wihb, const float* __restrict__ Whhb,
             const float* __restrict__ bihb, const float* __restrict__ bhhb,
             const float* __restrict__ linW, const float* __restrict__ linb) {
    const int tid = threadIdx.x;

    if (blockIdx.x >= LSTM_BLKS) {
        // ================= ELL build (spill-exact) =================
        int i = (blockIdx.x - LSTM_BLKS) * 512 + tid;
        if (i >= N_ / 4) return;
        int4 h = h4[i], t = t4[i], r = r4[i], t2 = t24[i];
#define DO1(hx, tx, rx, t2x) { \
        int pos = atomicAdd(&gZ.cnt_h[hx], 1); \
        unsigned pay = (unsigned)(tx) | ((unsigned)(rx) << 16); \
        if (pos < CAP_) g_ell_h[(size_t)(hx) * CAP_ + pos] = pay; \
        else { int sp = atomicAdd(&gZ.spill, 1); g_sp_ent[sp] = (hx); g_sp_pay[sp] = pay; } \
        int pos2 = atomicAdd(&gZ.cnt_t[t2x], 1); \
        unsigned pay2 = (unsigned)(hx) | ((unsigned)(rx) << 16); \
        if (pos2 < CAP_) g_ell_t[(size_t)(t2x) * CAP_ + pos2] = pay2; \
        else { int sp = atomicAdd(&gZ.spill, 1); g_sp_ent[sp] = (t2x); g_sp_pay[sp] = pay2 | 0x80000000u; } }
        DO1(h.x, t.x, r.x, t2.x); DO1(h.y, t.y, r.y, t2.y);
        DO1(h.z, t.z, r.z, t2.z); DO1(h.w, t.w, r.w, t2.w);
#undef DO1
        return;
    }

    // ================= BiLSTM + logits + softmax =================
    const int bid = blockIdx.x;                    // 0..95
    const int gid = bid * 512 + tid;
    __shared__ float s_buf[416];
    __shared__ float s_red[512];

    // --- pre: input projections for q and emb[-1] ---
    {
        int p = gid & 7, row = gid >> 3;           // 49152 threads exactly
        int ld = row >> 10, j = row & 1023;
        int dir = ld / 3, l = ld - dir * 3;
        const float4* w4 = (const float4*)((dir ? Wihb : Wihf) + ((size_t)(l * G_ + j)) * H_) + p * 8;
        const float4* e4 = (const float4*)(emb + (size_t)(NREL_ - 1) * H_) + p * 8;
        const float4* q4[B_];
        float aq[B_];
#pragma unroll
        for (int b = 0; b < B_; ++b) {
            q4[b] = (const float4*)(emb + (size_t)input_r[b] * H_) + p * 8;
            aq[b] = 0.f;
        }
        float ae = 0.f;
#pragma unroll
        for (int k = 0; k < 8; ++k) {
            float4 w = w4[k], e = e4[k];
            ae += w.x * e.x + w.y * e.y + w.z * e.z + w.w * e.w;
#pragma unroll
            for (int b = 0; b < B_; ++b) {
                float4 q = q4[b][k];
                aq[b] += w.x * q.x + w.y * q.y + w.z * q.z + w.w * q.w;
            }
        }
#pragma unroll
        for (int o = 1; o <= 4; o <<= 1) {
            ae += __shfl_xor_sync(0xffffffffu, ae, o);
#pragma unroll
            for (int b = 0; b < B_; ++b) aq[b] += __shfl_xor_sync(0xffffffffu, aq[b], o);
        }
        if (p == 0) {
            float bias = (dir ? bihb : bihf)[l * G_ + j] + (dir ? bhhb : bhhf)[l * G_ + j];
#pragma unroll
            for (int b = 0; b < B_; ++b) {
                int idx = (ld * 8 + b) * G_ + j;
                g_preq[idx] = aq[b] + bias;
                g_pree[idx] = ae + bias;
            }
        }
    }
    gridbar96();

    // --- 4 recurrence steps ---
    for (int s = 0; s < 4; ++s) {
        if (s > 0) {
            int p = gid & 7, row = gid >> 3;
            int ld = row >> 10, j = row & 1023;
            int dir = ld / 3, l = ld - dir * 3;
            const float4* w4 = (const float4*)((dir ? Whhb : Whhf) + ((size_t)(l * G_ + j)) * H_) + p * 8;
            const float4* hb = (const float4*)g_hst + (ld * 8) * 64 + p * 8;
            float acc[B_];
#pragma unroll
            for (int b = 0; b < B_; ++b) acc[b] = 0.f;
#pragma unroll
            for (int k = 0; k < 8; ++k) {
                float4 w = w4[k];
#pragma unroll
                for (int b = 0; b < B_; ++b) {
                    float4 h = hb[b * 64 + k];
                    acc[b] += w.x * h.x + w.y * h.y + w.z * h.z + w.w * h.w;
                }
            }
#pragma unroll
            for (int o = 1; o <= 4; o <<= 1)
#pragma unroll
                for (int b = 0; b < B_; ++b) acc[b] += __shfl_xor_sync(0xffffffffu, acc[b], o);
            if (p == 0) {
                const float* pre = ((dir == 0) && (s == 3)) ? g_pree : g_preq;
#pragma unroll
                for (int b = 0; b < B_; ++b) {
                    int idx = (ld * 8 + b) * G_ + j;
                    g_gates[idx] = pre[idx] + acc[b];
                }
            }
            gridbar96();
        }
        if (gid < 6 * B_ * H_) {
            int idx = gid;
            int ld = idx >> 11;
            int b  = (idx >> 8) & 7;
            int u  = idx & 255;
            int base2 = (ld * 8 + b) * G_;
            float gi, gf, gg, go, cprev;
            if (s == 0) {
                const float* src = (ld >= 3) ? g_pree : g_preq;   // bwd step0 sees emb[-1]
                gi = src[base2 + u]; gf = src[base2 + 256 + u];
                gg = src[base2 + 512 + u]; go = src[base2 + 768 + u];
                cprev = 0.f;
            } else {
                gi = g_gates[base2 + u]; gf = g_gates[base2 + 256 + u];
                gg = g_gates[base2 + 512 + u]; go = g_gates[base2 + 768 + u];
                cprev = g_cst[idx];
            }
            float c = sigm(gf) * cprev + sigm(gi) * tanhf(gg);
            float h = sigm(go) * tanhf(c);
            g_cst[idx] = c;
            g_hst[idx] = h;
            g_hseq[((ld * 4 + s) * 8 + b) * H_ + u] = h;
        }
        gridbar96();
    }

    // --- logits ---
    {
        const int TOTAL = NREL_ * 9 * 8;   // 28872
        int g = (gid < TOTAL) ? gid : (TOTAL - 1);
        int n = g / 72;
        int rem = g % 72;
        int tl = rem >> 3;
        int p = g & 7;
        int t = tl / 3, l = tl - t * 3;
        const float4* w1 = (const float4*)(linW + (size_t)n * 2 * H_) + p * 8;
        const float4* w2 = w1 + 64;
        const float4* hf = (const float4*)g_hseq + ((l * 4 + t) * 8) * 64 + p * 8;
        const float4* hb = (const float4*)g_hseq + (((3 + l) * 4 + (3 - t)) * 8) * 64 + p * 8;
        float acc[B_];
#pragma unroll
        for (int b = 0; b < B_; ++b) acc[b] = 0.f;
#pragma unroll
        for (int k = 0; k < 8; ++k) {
            float4 wa = w1[k], wb = w2[k];
#pragma unroll
            for (int b = 0; b < B_; ++b) {
                float4 a = hf[b * 64 + k];
                float4 c = hb[b * 64 + k];
                acc[b] += a.x * wa.x + a.y * wa.y + a.z * wa.z + a.w * wa.w
                        + c.x * wb.x + c.y * wb.y + c.z * wb.z + c.w * wb.w;
            }
        }
#pragma unroll
        for (int o = 1; o <= 4; o <<= 1)
#pragma unroll
            for (int b = 0; b < B_; ++b) acc[b] += __shfl_xor_sync(0xffffffffu, acc[b], o);
        if (gid < TOTAL && p == 0) {
            float bb = linb[n];
#pragma unroll
            for (int b = 0; b < B_; ++b)
                g_logits[(t * BL_ + b * 3 + l) * NREL_ + n] = acc[b] + bb;
        }
    }
    gridbar96();

    // --- softmax (72 rows over first 72 lstm blocks) ---
    if (bid < T_ * BL_) {
        const float* lg = g_logits + bid * NREL_;
        float* wout = g_w + bid * NREL_;
        float lmax = -1e30f;
        for (int i = tid; i < NREL_; i += 512) {
            float v = lg[i] * 0.1f;
            s_buf[i] = v;
            lmax = fmaxf(lmax, v);
        }
        s_red[tid] = lmax; __syncthreads();
        for (int o = 256; o > 0; o >>= 1) { if (tid < o) s_red[tid] = fmaxf(s_red[tid], s_red[tid + o]); __syncthreads(); }
        float m = s_red[0];
        __syncthreads();
        float lsum = 0.f;
        for (int i = tid; i < NREL_; i += 512) {
            float ex = expf(s_buf[i] - m);
            s_buf[i] = ex;
            lsum += ex;
        }
        s_red[tid] = lsum; __syncthreads();
        for (int o = 256; o > 0; o >>= 1) { if (tid < o) s_red[tid] += s_red[tid + o]; __syncthreads(); }
        float inv = 1.f / s_red[0];
        for (int i = tid; i < NREL_; i += 512) wout[i] = s_buf[i] * inv;
    }
}

// ---------------- fused hops: one block per (b,l), dense state in SMEM ----------------
// t<T-1: warp-per-entry propagate WITH first-touch tracking -> sparse select/compact/zero.
// t=T-1: tracking-free propagate + dense output scan. Normalizer via per-thread lsum.
__global__ void __launch_bounds__(HTPB, 1)
hops_kernel(const int* __restrict__ input_x, float* __restrict__ out) {
    extern __shared__ float s_state[];              // E_ floats = 200 KB
    __shared__ float    s_wr[NREL_];
    __shared__ unsigned s_fre[FRCAP];
    __shared__ float    s_frv[FRCAP];
    __shared__ int      s_hist[256];
    __shared__ float    s_wred[32];
    __shared__ float    s_nrm;
    __shared__ int      s_frc, s_cand;
    __shared__ unsigned shp, shm;
    __shared__ int      shk;

    const int bl = blockIdx.x, tid = threadIdx.x;
    const int lane = tid & 31, wid = tid >> 5;      // 32 warps
    int* cand = g_cand + (size_t)bl * E_;
    const int sc = gZ.spill;

    // zero state
    float4* st4 = (float4*)s_state;
    for (int i = tid; i < E_ / 4; i += HTPB) st4[i] = make_float4(0.f, 0.f, 0.f, 0.f);
    if (tid == 0) {
        s_frc = 1; s_cand = 0;
        s_fre[0] = (unsigned)input_x[bl / 3];
        s_frv[0] = 1.f;
    }
    __syncthreads();

    float nrm_prev = 1.f;                           // t=0: x0 used unnormalized
    for (int t = 0; t < T_; ++t) {
        // stage softmaxed relation weights in smem
        for (int i = tid; i < NREL_; i += HTPB) s_wr[i] = g_w[(t * BL_ + bl) * NREL_ + i];
        __syncthreads();
        const float inv = 1.f / fmaxf(nrm_prev, 1e-7f);
        const int fcnt = s_frc;
        const bool track = (t < T_ - 1);
        float lsum = 0.f;

        // ---------------- propagate: warp per frontier entry ----------------
        for (int ent = wid; ent < fcnt; ent += 32) {
            unsigned e; float fv;
            if (ent < FRCAP) { e = s_fre[ent]; fv = s_frv[ent]; }
            else { e = (unsigned)g_fr_ovf_e[(size_t)bl * E_ + ent]; fv = g_fr_ovf_v[(size_t)bl * E_ + ent]; }
            float v = fv * inv;

            // identity relation (lane 0) — full-warp ballot for tracking
            {
                bool first = false;
                if (lane == 0) {
                    float m = s_wr[NREL_ - 1] * v;
                    float old = atomicAdd(&s_state[e], m);
                    lsum += m;
                    first = (old == 0.f) && (m > 0.f);
                }
                if (track) {
                    unsigned bm = __ballot_sync(0xffffffffu, first);
                    if (bm && lane == 0) { int p = atomicAdd(&s_cand, 1); cand[p] = (int)e; }
                }
            }

            int ch = min(gZ.cnt_h[e], CAP_);
            const unsigned* row = g_ell_h + (size_t)e * CAP_;
            for (int i0 = 0; i0 < ch; i0 += 32) {
                int i = i0 + lane;
                bool act = (i < ch);
                unsigned pk = act ? row[i] : 0u;
                bool first = false;
                if (act) {
                    float m = v * s_wr[pk >> 16];
                    float old = atomicAdd(&s_state[pk & 0xFFFFu], m);
                    lsum += m;
                    first = (old == 0.f) && (m > 0.f);
                }
                if (track) {
                    unsigned bm = __ballot_sync(0xffffffffu, first);
                    if (bm) {
                        int ldr = (int)(__ffs(bm) - 1), base;
                        if (lane == ldr) base = atomicAdd(&s_cand, __popc(bm));
                        base = __shfl_sync(0xffffffffu, base, ldr);
                        if (first) cand[base + __popc(bm & ((1u << lane) - 1u))] = (int)(pk & 0xFFFFu);
                    }
                }
            }

            int ct = min(gZ.cnt_t[e], CAP_);
            row = g_ell_t + (size_t)e * CAP_;
            for (int i0 = 0; i0 < ct; i0 += 32) {
                int i = i0 + lane;
                bool act = (i < ct);
                unsigned pk = act ? row[i] : 0u;
                bool first = false;
                if (act) {
                    float m = v * s_wr[(pk >> 16) + R_];
                    float old = atomicAdd(&s_state[pk & 0xFFFFu], m);
                    lsum += m;
                    first = (old == 0.f) && (m > 0.f);
                }
                if (track) {
                    unsigned bm = __ballot_sync(0xffffffffu, first);
                    if (bm) {
                        int ldr = (int)(__ffs(bm) - 1), base;
                        if (lane == ldr) base = atomicAdd(&s_cand, __popc(bm));
                        base = __shfl_sync(0xffffffffu, base, ldr);
                        if (first) cand[base + __popc(bm & ((1u << lane) - 1u))] = (int)(pk & 0xFFFFu);
                    }
                }
            }

            if (sc) {
                for (int i0 = 0; i0 < sc; i0 += 32) {
                    int i = i0 + lane;
                    bool act = (i < sc) && ((unsigned)g_sp_ent[i] == e);
                    unsigned pk = act ? g_sp_pay[i] : 0u;
                    bool first = false;
                    if (act) {
                        int widx = (int)((pk >> 16) & 0x7FFFu) + ((pk >> 31) ? R_ : 0);
                        float m = v * s_wr[widx];
                        float old = atomicAdd(&s_state[pk & 0xFFFFu], m);
                        lsum += m;
                        first = (old == 0.f) && (m > 0.f);
                    }
                    if (track) {
                        unsigned bm = __ballot_sync(0xffffffffu, first);
                        if (bm) {
                            int ldr = (int)(__ffs(bm) - 1), base;
                            if (lane == ldr) base = atomicAdd(&s_cand, __popc(bm));
                            base = __shfl_sync(0xffffffffu, base, ldr);
                            if (first) cand[base + __popc(bm & ((1u << lane) - 1u))] = (int)(pk & 0xFFFFu);
                        }
                    }
                }
            }
        }
        // block-reduce lsum -> s_nrm
#pragma unroll
        for (int o = 16; o > 0; o >>= 1) lsum += __shfl_down_sync(0xffffffffu, lsum, o);
        if (lane == 0) s_wred[wid] = lsum;
        __syncthreads();
        if (wid == 0) {
            float a = s_wred[lane];
#pragma unroll
            for (int o = 16; o > 0; o >>= 1) a += __shfl_down_sync(0xffffffffu, a, o);
            if (lane == 0) s_nrm = a;
        }
        __syncthreads();
        const float nrm_out = s_nrm;

        if (t == T_ - 1) {
            // dense output scan: out[b] += state/nrm (3 channels per b -> atomics)
            float invo = 1.f / fmaxf(nrm_out, 1e-7f);
            float* ob = out + (size_t)(bl / 3) * E_;
            for (int i = tid; i < E_; i += HTPB) {
                float v = s_state[i];
                if (v != 0.f) atomicAdd(&ob[i], v * invo);
            }
        } else {
            const int nnz = s_cand;
            // exact top-k threshold via radix select over candidate list (values > 0)
            float th = 0.f;
            if (nnz > TOPK_) {
                if (tid == 0) { shp = 0u; shm = 0u; shk = TOPK_; }
                __syncthreads();
                for (int pass = 0; pass < 4; ++pass) {
                    int shift = 24 - 8 * pass;
                    if (tid < 256) s_hist[tid] = 0;
                    __syncthreads();
                    unsigned mask = shm, pref = shp;
                    for (int i0 = 0; i0 < nnz; i0 += HTPB) {
                        int i = i0 + tid;
                        bool act = (i < nnz);
                        unsigned bits = act ? __float_as_uint(s_state[cand[i]]) : 0u;
                        bool ok = act && ((bits & mask) == pref);
                        int bin = (bits >> shift) & 255;
                        unsigned am = __ballot_sync(0xffffffffu, ok);
                        if (ok) {
                            unsigned mm = __match_any_sync(am, bin);
                            if (lane == (int)(__ffs(mm) - 1)) atomicAdd(&s_hist[bin], __popc(mm));
                        }
                    }
                    __syncthreads();
                    if (tid == 0) {
                        int cum = 0, krem = shk, sel = 0, newk = krem;
                        for (int bn = 255; bn >= 0; --bn) {
                            int c = s_hist[bn];
                            if (cum + c >= krem) { sel = bn; newk = krem - cum; break; }
                            cum += c;
                        }
                        shp = pref | ((unsigned)sel << shift);
                        shm = mask | (0xFFu << shift);
                        shk = newk;
                    }
                    __syncthreads();
                }
                th = __uint_as_float(shp);
            }
            __syncthreads();
            if (tid == 0) s_frc = 0;
            __syncthreads();
            // sparse compact over candidates (keep v >= th) + zero consumed entries
            for (int i0 = 0; i0 < nnz; i0 += HTPB) {
                int i = i0 + tid;
                bool act = (i < nnz);
                int e = act ? cand[i] : 0;
                float v = act ? s_state[e] : 0.f;
                bool keep = act && (v >= th) && (v > 0.f);
                unsigned bm = __ballot_sync(0xffffffffu, keep);
                if (bm) {
                    int ldr = (int)(__ffs(bm) - 1), base;
                    if (lane == ldr) base = atomicAdd(&s_frc, __popc(bm));
                    base = __shfl_sync(0xffffffffu, base, ldr);
                    if (keep) {
                        int p = base + __popc(bm & ((1u << lane) - 1u));
                        if (p < FRCAP) { s_fre[p] = (unsigned)e; s_frv[p] = v; }
                        else { g_fr_ovf_e[(size_t)bl * E_ + p] = e; g_fr_ovf_v[(size_t)bl * E_ + p] = v; }
                    }
                }
                if (act) s_state[e] = 0.f;
            }
            __syncthreads();
            if (tid == 0) s_cand = 0;
            nrm_prev = nrm_out;
            __syncthreads();
        }
    }
}

// ---------------- launch (single stream, 4 linear nodes) ----------------
extern "C" void kernel_launch(void* const* d_in, const int* in_sizes, int n_in,
                              void* d_out, int out_size) {
    (void)in_sizes; (void)n_in; (void)out_size;
    const int*   input_x = (const int*)d_in[0];
    const int*   input_r = (const int*)d_in[1];
    const int*   e2      = (const int*)d_in[2];
    const int*   t2e     = (const int*)d_in[3];
    const int*   r2      = (const int*)d_in[4];
    const float* emb     = (const float*)d_in[5];

    static bool init = false;
    if (!init) {
        cudaFuncSetAttribute(hops_kernel, cudaFuncAttributeMaxDynamicSharedMemorySize, E_ * 4);
        init = true;
    }

    void* pZ;
    cudaGetSymbolAddress(&pZ, gZ);

    cudaMemsetAsync(pZ, 0, sizeof(Zs), 0);
    cudaMemsetAsync(d_out, 0, (size_t)B_ * E_ * sizeof(float), 0);

    // BiLSTM (96 blocks, placed first) + build (489 blocks), overlapped in one launch
    combo_kernel<<<LSTM_BLKS + BUILD_BLKS, 512>>>(
        (const int4*)e2, (const int4*)(t2e + N_), (const int4*)r2, (const int4*)(e2 + 2 * N_),
        input_r, emb,
        (const float*)d_in[6], (const float*)d_in[7], (const float*)d_in[8],
        (const float*)d_in[9], (const float*)d_in[10], (const float*)d_in[11],
        (const float*)d_in[12], (const float*)d_in[13], (const float*)d_in[14],
        (const float*)d_in[15]);

    // fused hops: all 3 propagation rounds + top-k + output, per-(b,l) block
    hops_kernel<<<BL_, HTPB, E_ * 4>>>(input_x, (float*)d_out);
}

// round 16
// speedup vs baseline: 1.1666x; 1.0188x over previous
#include <cuda_runtime.h>
#include <math.h>
#include <cstddef>

#define E_    50000
#define N_    1000000
#define B_    8
#define L_    3
#define T_    3
#define NREL_ 401
#define R_    200
#define H_    256
#define G_    1024
#define TOPK_ 1000
#define BL_   24
#define CAP_  64
#define FRCAP 2048
#define LSTM_BLKS  96
#define BUILD_BLKS 489            // ceil(250000/512)
#define HTPB 1024

// ---------------- zeroed-every-launch block (single memset) ----------------
struct Zs {
    int cnt_h[E_];
    int cnt_t[E_];
    int spill;
};
__device__ Zs gZ;

// ---------------- persistent scratch ----------------
__device__ unsigned g_ell_h[(size_t)E_ * CAP_];   // tail | (rel<<16)
__device__ unsigned g_ell_t[(size_t)E_ * CAP_];   // head | (rel<<16)
__device__ int      g_sp_ent[2 * N_];
__device__ unsigned g_sp_pay[2 * N_];             // tgt | (rel<<16) | (dir<<31)
__device__ int      g_cand[(size_t)BL_ * E_];     // per-bl candidate lists (t < T-1 only)
__device__ unsigned g_fr_ovf_e[(size_t)BL_ * E_]; // frontier overflow (packed)
__device__ float    g_fr_ovf_v[(size_t)BL_ * E_];
// lstm
__device__ float    g_preq[6 * B_ * G_], g_pree[6 * B_ * G_], g_gates[6 * B_ * G_];
__device__ float    g_hst[6 * B_ * H_], g_cst[6 * B_ * H_];
__device__ float    g_hseq[24 * B_ * H_];
__device__ float    g_logits[T_ * BL_ * NREL_], g_w[T_ * BL_ * NREL_];

__device__ unsigned g_bar_cnt = 0;
__device__ volatile unsigned g_bar_gen = 0;

__device__ __forceinline__ float sigm(float x) { return 1.f / (1.f + expf(-x)); }

// sub-grid barrier over exactly LSTM_BLKS blocks (build blocks never touch it;
// they always retire, so all LSTM blocks become co-resident -> no deadlock)
__device__ __forceinline__ void gridbar96() {
    __threadfence();
    __syncthreads();
    if (threadIdx.x == 0) {
        unsigned gen = g_bar_gen;
        if (atomicAdd(&g_bar_cnt, 1u) == LSTM_BLKS - 1) {
            g_bar_cnt = 0;
            __threadfence();
            g_bar_gen = gen + 1;
        } else {
            while (g_bar_gen == gen) __nanosleep(40);
        }
    }
    __syncthreads();
}

// ---------------- combined: BiLSTM (blocks 0..95) + ELL build (blocks 96..584) ----------------
__global__ void __launch_bounds__(512)
combo_kernel(const int4* __restrict__ h4, const int4* __restrict__ t4,
             const int4* __restrict__ r4, const int4* __restrict__ t24,
             const int* __restrict__ input_r, const float* __restrict__ emb,
             const float* __restrict__ Wihf, const float* __restrict__ Whhf,
             const float* __restrict__ bihf, const float* __restrict__ bhhf,
             const float* __restrict__ Wihb, const float* __restrict__ Whhb,
             const float* __restrict__ bihb, const float* __restrict__ bhhb,
             const float* __restrict__ linW, const float* __restrict__ linb) {
    const int tid = threadIdx.x;

    if (blockIdx.x >= LSTM_BLKS) {
        // ================= ELL build (spill-exact) =================
        int i = (blockIdx.x - LSTM_BLKS) * 512 + tid;
        if (i >= N_ / 4) return;
        int4 h = h4[i], t = t4[i], r = r4[i], t2 = t24[i];
#define DO1(hx, tx, rx, t2x) { \
        int pos = atomicAdd(&gZ.cnt_h[hx], 1); \
        unsigned pay = (unsigned)(tx) | ((unsigned)(rx) << 16); \
        if (pos < CAP_) g_ell_h[(size_t)(hx) * CAP_ + pos] = pay; \
        else { int sp = atomicAdd(&gZ.spill, 1); g_sp_ent[sp] = (hx); g_sp_pay[sp] = pay; } \
        int pos2 = atomicAdd(&gZ.cnt_t[t2x], 1); \
        unsigned pay2 = (unsigned)(hx) | ((unsigned)(rx) << 16); \
        if (pos2 < CAP_) g_ell_t[(size_t)(t2x) * CAP_ + pos2] = pay2; \
        else { int sp = atomicAdd(&gZ.spill, 1); g_sp_ent[sp] = (t2x); g_sp_pay[sp] = pay2 | 0x80000000u; } }
        DO1(h.x, t.x, r.x, t2.x); DO1(h.y, t.y, r.y, t2.y);
        DO1(h.z, t.z, r.z, t2.z); DO1(h.w, t.w, r.w, t2.w);
#undef DO1
        return;
    }

    // ================= BiLSTM + logits + softmax =================
    const int bid = blockIdx.x;                    // 0..95
    const int gid = bid * 512 + tid;
    __shared__ float s_buf[416];
    __shared__ float s_red[512];

    // --- pre: input projections for q and emb[-1] ---
    {
        int p = gid & 7, row = gid >> 3;           // 49152 threads exactly
        int ld = row >> 10, j = row & 1023;
        int dir = ld / 3, l = ld - dir * 3;
        const float4* w4 = (const float4*)((dir ? Wihb : Wihf) + ((size_t)(l * G_ + j)) * H_) + p * 8;
        const float4* e4 = (const float4*)(emb + (size_t)(NREL_ - 1) * H_) + p * 8;
        const float4* q4[B_];
        float aq[B_];
#pragma unroll
        for (int b = 0; b < B_; ++b) {
            q4[b] = (const float4*)(emb + (size_t)input_r[b] * H_) + p * 8;
            aq[b] = 0.f;
        }
        float ae = 0.f;
#pragma unroll
        for (int k = 0; k < 8; ++k) {
            float4 w = w4[k], e = e4[k];
            ae += w.x * e.x + w.y * e.y + w.z * e.z + w.w * e.w;
#pragma unroll
            for (int b = 0; b < B_; ++b) {
                float4 q = q4[b][k];
                aq[b] += w.x * q.x + w.y * q.y + w.z * q.z + w.w * q.w;
            }
        }
#pragma unroll
        for (int o = 1; o <= 4; o <<= 1) {
            ae += __shfl_xor_sync(0xffffffffu, ae, o);
#pragma unroll
            for (int b = 0; b < B_; ++b) aq[b] += __shfl_xor_sync(0xffffffffu, aq[b], o);
        }
        if (p == 0) {
            float bias = (dir ? bihb : bihf)[l * G_ + j] + (dir ? bhhb : bhhf)[l * G_ + j];
#pragma unroll
            for (int b = 0; b < B_; ++b) {
                int idx = (ld * 8 + b) * G_ + j;
                g_preq[idx] = aq[b] + bias;
                g_pree[idx] = ae + bias;
            }
        }
    }
    gridbar96();

    // --- 4 recurrence steps ---
    for (int s = 0; s < 4; ++s) {
        if (s > 0) {
            int p = gid & 7, row = gid >> 3;
            int ld = row >> 10, j = row & 1023;
            int dir = ld / 3, l = ld - dir * 3;
            const float4* w4 = (const float4*)((dir ? Whhb : Whhf) + ((size_t)(l * G_ + j)) * H_) + p * 8;
            const float4* hb = (const float4*)g_hst + (ld * 8) * 64 + p * 8;
            float acc[B_];
#pragma unroll
            for (int b = 0; b < B_; ++b) acc[b] = 0.f;
#pragma unroll
            for (int k = 0; k < 8; ++k) {
                float4 w = w4[k];
#pragma unroll
                for (int b = 0; b < B_; ++b) {
                    float4 h = hb[b * 64 + k];
                    acc[b] += w.x * h.x + w.y * h.y + w.z * h.z + w.w * h.w;
                }
            }
#pragma unroll
            for (int o = 1; o <= 4; o <<= 1)
#pragma unroll
                for (int b = 0; b < B_; ++b) acc[b] += __shfl_xor_sync(0xffffffffu, acc[b], o);
            if (p == 0) {
                const float* pre = ((dir == 0) && (s == 3)) ? g_pree : g_preq;
#pragma unroll
                for (int b = 0; b < B_; ++b) {
                    int idx = (ld * 8 + b) * G_ + j;
                    g_gates[idx] = pre[idx] + acc[b];
                }
            }
            gridbar96();
        }
        if (gid < 6 * B_ * H_) {
            int idx = gid;
            int ld = idx >> 11;
            int b  = (idx >> 8) & 7;
            int u  = idx & 255;
            int base2 = (ld * 8 + b) * G_;
            float gi, gf, gg, go, cprev;
            if (s == 0) {
                const float* src = (ld >= 3) ? g_pree : g_preq;   // bwd step0 sees emb[-1]
                gi = src[base2 + u]; gf = src[base2 + 256 + u];
                gg = src[base2 + 512 + u]; go = src[base2 + 768 + u];
                cprev = 0.f;
            } else {
                gi = g_gates[base2 + u]; gf = g_gates[base2 + 256 + u];
                gg = g_gates[base2 + 512 + u]; go = g_gates[base2 + 768 + u];
                cprev = g_cst[idx];
            }
            float c = sigm(gf) * cprev + sigm(gi) * tanhf(gg);
            float h = sigm(go) * tanhf(c);
            g_cst[idx] = c;
            g_hst[idx] = h;
            g_hseq[((ld * 4 + s) * 8 + b) * H_ + u] = h;
        }
        gridbar96();
    }

    // --- logits ---
    {
        const int TOTAL = NREL_ * 9 * 8;   // 28872
        int g = (gid < TOTAL) ? gid : (TOTAL - 1);
        int n = g / 72;
        int rem = g % 72;
        int tl = rem >> 3;
        int p = g & 7;
        int t = tl / 3, l = tl - t * 3;
        const float4* w1 = (const float4*)(linW + (size_t)n * 2 * H_) + p * 8;
        const float4* w2 = w1 + 64;
        const float4* hf = (const float4*)g_hseq + ((l * 4 + t) * 8) * 64 + p * 8;
        const float4* hb = (const float4*)g_hseq + (((3 + l) * 4 + (3 - t)) * 8) * 64 + p * 8;
        float acc[B_];
#pragma unroll
        for (int b = 0; b < B_; ++b) acc[b] = 0.f;
#pragma unroll
        for (int k = 0; k < 8; ++k) {
            float4 wa = w1[k], wb = w2[k];
#pragma unroll
            for (int b = 0; b < B_; ++b) {
                float4 a = hf[b * 64 + k];
                float4 c = hb[b * 64 + k];
                acc[b] += a.x * wa.x + a.y * wa.y + a.z * wa.z + a.w * wa.w
                        + c.x * wb.x + c.y * wb.y + c.z * wb.z + c.w * wb.w;
            }
        }
#pragma unroll
        for (int o = 1; o <= 4; o <<= 1)
#pragma unroll
            for (int b = 0; b < B_; ++b) acc[b] += __shfl_xor_sync(0xffffffffu, acc[b], o);
        if (gid < TOTAL && p == 0) {
            float bb = linb[n];
#pragma unroll
            for (int b = 0; b < B_; ++b)
                g_logits[(t * BL_ + b * 3 + l) * NREL_ + n] = acc[b] + bb;
        }
    }
    gridbar96();

    // --- softmax (72 rows over first 72 lstm blocks) ---
    if (bid < T_ * BL_) {
        const float* lg = g_logits + bid * NREL_;
        float* wout = g_w + bid * NREL_;
        float lmax = -1e30f;
        for (int i = tid; i < NREL_; i += 512) {
            float v = lg[i] * 0.1f;
            s_buf[i] = v;
            lmax = fmaxf(lmax, v);
        }
        s_red[tid] = lmax; __syncthreads();
        for (int o = 256; o > 0; o >>= 1) { if (tid < o) s_red[tid] = fmaxf(s_red[tid], s_red[tid + o]); __syncthreads(); }
        float m = s_red[0];
        __syncthreads();
        float lsum = 0.f;
        for (int i = tid; i < NREL_; i += 512) {
            float ex = expf(s_buf[i] - m);
            s_buf[i] = ex;
            lsum += ex;
        }
        s_red[tid] = lsum; __syncthreads();
        for (int o = 256; o > 0; o >>= 1) { if (tid < o) s_red[tid] += s_red[tid + o]; __syncthreads(); }
        float inv = 1.f / s_red[0];
        for (int i = tid; i < NREL_; i += 512) wout[i] = s_buf[i] * inv;
    }
}

// ---------------- fused hops: one block per (b,l), dense state in SMEM ----------------
// Frontier entries are PACKED: e | min(cnt_h,64)<<16 | min(cnt_t,64)<<23 —
// counts prefetched at compact time, so propagate has no cnt loads.
// Propagate unit = (entry, direction-half): one ELL row per unit -> 2x parallelism.
__global__ void __launch_bounds__(HTPB, 1)
hops_kernel(const int* __restrict__ input_x, float* __restrict__ out) {
    extern __shared__ float s_state[];              // E_ floats = 200 KB
    __shared__ float    s_wr[NREL_];
    __shared__ unsigned s_fre[FRCAP];
    __shared__ float    s_frv[FRCAP];
    __shared__ int      s_hist[256];
    __shared__ float    s_wred[32];
    __shared__ float    s_nrm;
    __shared__ int      s_frc, s_cand;
    __shared__ unsigned shp, shm;
    __shared__ int      shk;

    const int bl = blockIdx.x, tid = threadIdx.x;
    const int lane = tid & 31, wid = tid >> 5;      // 32 warps
    int* cand = g_cand + (size_t)bl * E_;
    const int sc = gZ.spill;

    // zero state
    float4* st4 = (float4*)s_state;
    for (int i = tid; i < E_ / 4; i += HTPB) st4[i] = make_float4(0.f, 0.f, 0.f, 0.f);
    if (tid == 0) {
        s_frc = 1; s_cand = 0;
        unsigned e = (unsigned)input_x[bl / 3];
        unsigned ch = (unsigned)min(gZ.cnt_h[e], CAP_);
        unsigned ct = (unsigned)min(gZ.cnt_t[e], CAP_);
        s_fre[0] = e | (ch << 16) | (ct << 23);
        s_frv[0] = 1.f;
    }
    __syncthreads();

    float nrm_prev = 1.f;                           // t=0: x0 used unnormalized
    for (int t = 0; t < T_; ++t) {
        // stage softmaxed relation weights in smem
        for (int i = tid; i < NREL_; i += HTPB) s_wr[i] = g_w[(t * BL_ + bl) * NREL_ + i];
        __syncthreads();
        const float inv = 1.f / fmaxf(nrm_prev, 1e-7f);
        const int fcnt = s_frc;
        const bool track = (t < T_ - 1);
        float lsum = 0.f;

        // ---------------- propagate: warp per (entry, half) unit ----------------
        for (int u = wid; u < 2 * fcnt; u += 32) {
            int ent = u >> 1;
            int half = u & 1;                        // 0: head-dir, 1: tail-dir
            unsigned pe; float fv;
            if (ent < FRCAP) { pe = s_fre[ent]; fv = s_frv[ent]; }
            else { pe = g_fr_ovf_e[(size_t)bl * E_ + ent]; fv = g_fr_ovf_v[(size_t)bl * E_ + ent]; }
            unsigned e = pe & 0xFFFFu;
            int cnt = half ? (int)((pe >> 23) & 0x7Fu) : (int)((pe >> 16) & 0x7Fu);
            const unsigned* row = (half ? g_ell_t : g_ell_h) + (size_t)e * CAP_;
            const int rbase = half ? R_ : 0;
            float v = fv * inv;

            // identity relation (half 0, lane 0) — full-warp ballot for tracking
            {
                bool first = false;
                if (half == 0 && lane == 0) {
                    float m = s_wr[NREL_ - 1] * v;
                    float old = atomicAdd(&s_state[e], m);
                    lsum += m;
                    first = (old == 0.f) && (m > 0.f);
                }
                if (track) {
                    unsigned bm = __ballot_sync(0xffffffffu, first);
                    if (bm && lane == 0 && first) { int p = atomicAdd(&s_cand, 1); cand[p] = (int)e; }
                }
            }

            for (int i0 = 0; i0 < cnt; i0 += 32) {
                int i = i0 + lane;
                bool act = (i < cnt);
                unsigned pk = act ? row[i] : 0u;
                bool first = false;
                if (act) {
                    float m = v * s_wr[(pk >> 16) + rbase];
                    float old = atomicAdd(&s_state[pk & 0xFFFFu], m);
                    lsum += m;
                    first = (old == 0.f) && (m > 0.f);
                }
                if (track) {
                    unsigned bm = __ballot_sync(0xffffffffu, first);
                    if (bm) {
                        int ldr = (int)(__ffs(bm) - 1), base;
                        if (lane == ldr) base = atomicAdd(&s_cand, __popc(bm));
                        base = __shfl_sync(0xffffffffu, base, ldr);
                        if (first) cand[base + __popc(bm & ((1u << lane) - 1u))] = (int)(pk & 0xFFFFu);
                    }
                }
            }

            if (sc) {
                for (int i0 = 0; i0 < sc; i0 += 32) {
                    int i = i0 + lane;
                    bool act = (i < sc) && ((unsigned)g_sp_ent[i] == e);
                    unsigned pk = act ? g_sp_pay[i] : 0u;
                    if (act) act = ((int)(pk >> 31) == half);
                    bool first = false;
                    if (act) {
                        int widx = (int)((pk >> 16) & 0x7FFFu) + rbase;
                        float m = v * s_wr[widx];
                        float old = atomicAdd(&s_state[pk & 0xFFFFu], m);
                        lsum += m;
                        first = (old == 0.f) && (m > 0.f);
                    }
                    if (track) {
                        unsigned bm = __ballot_sync(0xffffffffu, first);
                        if (bm) {
                            int ldr = (int)(__ffs(bm) - 1), base;
                            if (lane == ldr) base = atomicAdd(&s_cand, __popc(bm));
                            base = __shfl_sync(0xffffffffu, base, ldr);
                            if (first) cand[base + __popc(bm & ((1u << lane) - 1u))] = (int)(pk & 0xFFFFu);
                        }
                    }
                }
            }
        }
        // block-reduce lsum -> s_nrm
#pragma unroll
        for (int o = 16; o > 0; o >>= 1) lsum += __shfl_down_sync(0xffffffffu, lsum, o);
        if (lane == 0) s_wred[wid] = lsum;
        __syncthreads();
        if (wid == 0) {
            float a = s_wred[lane];
#pragma unroll
            for (int o = 16; o > 0; o >>= 1) a += __shfl_down_sync(0xffffffffu, a, o);
            if (lane == 0) s_nrm = a;
        }
        __syncthreads();
        const float nrm_out = s_nrm;

        if (t == T_ - 1) {
            // dense output scan: out[b] += state/nrm (3 channels per b -> atomics)
            float invo = 1.f / fmaxf(nrm_out, 1e-7f);
            float* ob = out + (size_t)(bl / 3) * E_;
            for (int i = tid; i < E_; i += HTPB) {
                float v = s_state[i];
                if (v != 0.f) atomicAdd(&ob[i], v * invo);
            }
        } else {
            const int nnz = s_cand;
            // exact top-k threshold via radix select over candidate list (values > 0)
            float th = 0.f;
            if (nnz > TOPK_) {
                if (tid == 0) { shp = 0u; shm = 0u; shk = TOPK_; }
                __syncthreads();
                for (int pass = 0; pass < 4; ++pass) {
                    int shift = 24 - 8 * pass;
                    if (tid < 256) s_hist[tid] = 0;
                    __syncthreads();
                    unsigned mask = shm, pref = shp;
                    for (int i0 = 0; i0 < nnz; i0 += HTPB) {
                        int i = i0 + tid;
                        bool act = (i < nnz);
                        unsigned bits = act ? __float_as_uint(s_state[cand[i]]) : 0u;
                        bool ok = act && ((bits & mask) == pref);
                        int bin = (bits >> shift) & 255;
                        unsigned am = __ballot_sync(0xffffffffu, ok);
                        if (ok) {
                            unsigned mm = __match_any_sync(am, bin);
                            if (lane == (int)(__ffs(mm) - 1)) atomicAdd(&s_hist[bin], __popc(mm));
                        }
                    }
                    __syncthreads();
                    if (tid == 0) {
                        int cum = 0, krem = shk, sel = 0, newk = krem;
                        for (int bn = 255; bn >= 0; --bn) {
                            int c = s_hist[bn];
                            if (cum + c >= krem) { sel = bn; newk = krem - cum; break; }
                            cum += c;
                        }
                        shp = pref | ((unsigned)sel << shift);
                        shm = mask | (0xFFu << shift);
                        shk = newk;
                    }
                    __syncthreads();
                }
                th = __uint_as_float(shp);
            }
            __syncthreads();
            if (tid == 0) s_frc = 0;
            __syncthreads();
            // sparse compact (keep v >= th) + count prefetch/pack + zero consumed entries
            for (int i0 = 0; i0 < nnz; i0 += HTPB) {
                int i = i0 + tid;
                bool act = (i < nnz);
                int e = act ? cand[i] : 0;
                float v = act ? s_state[e] : 0.f;
                bool keep = act && (v >= th) && (v > 0.f);
                unsigned packed = 0;
                if (keep) {
                    unsigned ch = (unsigned)min(gZ.cnt_h[e], CAP_);
                    unsigned ct = (unsigned)min(gZ.cnt_t[e], CAP_);
                    packed = (unsigned)e | (ch << 16) | (ct << 23);
                }
                unsigned bm = __ballot_sync(0xffffffffu, keep);
                if (bm) {
                    int ldr = (int)(__ffs(bm) - 1), base;
                    if (lane == ldr) base = atomicAdd(&s_frc, __popc(bm));
                    base = __shfl_sync(0xffffffffu, base, ldr);
                    if (keep) {
                        int p = base + __popc(bm & ((1u << lane) - 1u));
                        if (p < FRCAP) { s_fre[p] = packed; s_frv[p] = v; }
                        else { g_fr_ovf_e[(size_t)bl * E_ + p] = packed; g_fr_ovf_v[(size_t)bl * E_ + p] = v; }
                    }
                }
                if (act) s_state[e] = 0.f;
            }
            __syncthreads();
            if (tid == 0) s_cand = 0;
            nrm_prev = nrm_out;
            __syncthreads();
        }
    }
}

// ---------------- launch (single stream, 4 linear nodes) ----------------
extern "C" void kernel_launch(void* const* d_in, const int* in_sizes, int n_in,
                              void* d_out, int out_size) {
    (void)in_sizes; (void)n_in; (void)out_size;
    const int*   input_x = (const int*)d_in[0];
    const int*   input_r = (const int*)d_in[1];
    const int*   e2      = (const int*)d_in[2];
    const int*   t2e     = (const int*)d_in[3];
    const int*   r2      = (const int*)d_in[4];
    const float* emb     = (const float*)d_in[5];

    static bool init = false;
    if (!init) {
        cudaFuncSetAttribute(hops_kernel, cudaFuncAttributeMaxDynamicSharedMemorySize, E_ * 4);
        init = true;
    }

    void* pZ;
    cudaGetSymbolAddress(&pZ, gZ);

    cudaMemsetAsync(pZ, 0, sizeof(Zs), 0);
    cudaMemsetAsync(d_out, 0, (size_t)B_ * E_ * sizeof(float), 0);

    // BiLSTM (96 blocks, placed first) + build (489 blocks), overlapped in one launch
    combo_kernel<<<LSTM_BLKS + BUILD_BLKS, 512>>>(
        (const int4*)e2, (const int4*)(t2e + N_), (const int4*)r2, (const int4*)(e2 + 2 * N_),
        input_r, emb,
        (const float*)d_in[6], (const float*)d_in[7], (const float*)d_in[8],
        (const float*)d_in[9], (const float*)d_in[10], (const float*)d_in[11],
        (const float*)d_in[12], (const float*)d_in[13], (const float*)d_in[14],
        (const float*)d_in[15]);

    // fused hops: all 3 propagation rounds + top-k + output, per-(b,l) block
    hops_kernel<<<BL_, HTPB, E_ * 4>>>(input_x, (float*)d_out);
}

// round 17
// speedup vs baseline: 1.2692x; 1.0880x over previous
#include <cuda_runtime.h>
#include <math.h>
#include <cstddef>

#define E_    50000
#define N_    1000000
#define B_    8
#define L_    3
#define T_    3
#define NREL_ 401
#define R_    200
#define H_    256
#define G_    1024
#define TOPK_ 1000
#define BL_   24
#define CAP_  64
#define FRCAP 2048
#define LSTM_BLKS  96
#define BUILD_BLKS 489            // ceil(250000/512)
#define HTPB 1024
#define NSPL 6                    // hop-2 split factor (blocks per (b,l))

// ---------------- zeroed-every-launch block (single memset) ----------------
struct Zs {
    int   cnt_h[E_];
    int   cnt_t[E_];
    int   spill;
    float nrm2[BL_];
};
__device__ Zs gZ;

// ---------------- persistent scratch ----------------
__device__ unsigned g_ell_h[(size_t)E_ * CAP_];   // tail | (rel<<16)
__device__ unsigned g_ell_t[(size_t)E_ * CAP_];   // head | (rel<<16)
__device__ int      g_sp_ent[2 * N_];
__device__ unsigned g_sp_pay[2 * N_];             // tgt | (rel<<16) | (dir<<31)
__device__ int      g_cand[(size_t)BL_ * NSPL * 4096]; // per-block candidate lists (t0/t1: <=1.7K)
__device__ unsigned g_fr_ovf_e[(size_t)BL_ * NSPL * 4096];
__device__ float    g_fr_ovf_v[(size_t)BL_ * NSPL * 4096];
__device__ float    g_part[(size_t)BL_ * NSPL * E_];   // hop-2 partial states
// lstm
__device__ float    g_preq[6 * B_ * G_], g_pree[6 * B_ * G_], g_gates[6 * B_ * G_];
__device__ float    g_hst[6 * B_ * H_], g_cst[6 * B_ * H_];
__device__ float    g_hseq[24 * B_ * H_];
__device__ float    g_logits[T_ * BL_ * NREL_], g_w[T_ * BL_ * NREL_];

__device__ unsigned g_bar_cnt = 0;
__device__ volatile unsigned g_bar_gen = 0;

__device__ __forceinline__ float sigm(float x) { return 1.f / (1.f + expf(-x)); }

// sub-grid barrier over exactly LSTM_BLKS blocks (build blocks never touch it;
// they always retire, so all LSTM blocks become co-resident -> no deadlock)
__device__ __forceinline__ void gridbar96() {
    __threadfence();
    __syncthreads();
    if (threadIdx.x == 0) {
        unsigned gen = g_bar_gen;
        if (atomicAdd(&g_bar_cnt, 1u) == LSTM_BLKS - 1) {
            g_bar_cnt = 0;
            __threadfence();
            g_bar_gen = gen + 1;
        } else {
            while (g_bar_gen == gen) __nanosleep(40);
        }
    }
    __syncthreads();
}

// ---------------- combined: BiLSTM (blocks 0..95) + ELL build (blocks 96..584) ----------------
__global__ void __launch_bounds__(512)
combo_kernel(const int4* __restrict__ h4, const int4* __restrict__ t4,
             const int4* __restrict__ r4, const int4* __restrict__ t24,
             const int* __restrict__ input_r, const float* __restrict__ emb,
             const float* __restrict__ Wihf, const float* __restrict__ Whhf,
             const float* __restrict__ bihf, const float* __restrict__ bhhf,
             const float* __restrict__ Wihb, const float* __restrict__ Whhb,
             const float* __restrict__ bihb, const float* __restrict__ bhhb,
             const float* __restrict__ linW, const float* __restrict__ linb) {
    const int tid = threadIdx.x;

    if (blockIdx.x >= LSTM_BLKS) {
        // ================= ELL build (spill-exact) =================
        int i = (blockIdx.x - LSTM_BLKS) * 512 + tid;
        if (i >= N_ / 4) return;
        int4 h = h4[i], t = t4[i], r = r4[i], t2 = t24[i];
#define DO1(hx, tx, rx, t2x) { \
        int pos = atomicAdd(&gZ.cnt_h[hx], 1); \
        unsigned pay = (unsigned)(tx) | ((unsigned)(rx) << 16); \
        if (pos < CAP_) g_ell_h[(size_t)(hx) * CAP_ + pos] = pay; \
        else { int sp = atomicAdd(&gZ.spill, 1); g_sp_ent[sp] = (hx); g_sp_pay[sp] = pay; } \
        int pos2 = atomicAdd(&gZ.cnt_t[t2x], 1); \
        unsigned pay2 = (unsigned)(hx) | ((unsigned)(rx) << 16); \
        if (pos2 < CAP_) g_ell_t[(size_t)(t2x) * CAP_ + pos2] = pay2; \
        else { int sp = atomicAdd(&gZ.spill, 1); g_sp_ent[sp] = (t2x); g_sp_pay[sp] = pay2 | 0x80000000u; } }
        DO1(h.x, t.x, r.x, t2.x); DO1(h.y, t.y, r.y, t2.y);
        DO1(h.z, t.z, r.z, t2.z); DO1(h.w, t.w, r.w, t2.w);
#undef DO1
        return;
    }

    // ================= BiLSTM + logits + softmax =================
    const int bid = blockIdx.x;                    // 0..95
    const int gid = bid * 512 + tid;
    __shared__ float s_buf[416];
    __shared__ float s_red[512];

    // --- pre: input projections for q and emb[-1] ---
    {
        int p = gid & 7, row = gid >> 3;           // 49152 threads exactly
        int ld = row >> 10, j = row & 1023;
        int dir = ld / 3, l = ld - dir * 3;
        const float4* w4 = (const float4*)((dir ? Wihb : Wihf) + ((size_t)(l * G_ + j)) * H_) + p * 8;
        const float4* e4 = (const float4*)(emb + (size_t)(NREL_ - 1) * H_) + p * 8;
        const float4* q4[B_];
        float aq[B_];
#pragma unroll
        for (int b = 0; b < B_; ++b) {
            q4[b] = (const float4*)(emb + (size_t)input_r[b] * H_) + p * 8;
            aq[b] = 0.f;
        }
        float ae = 0.f;
#pragma unroll
        for (int k = 0; k < 8; ++k) {
            float4 w = w4[k], e = e4[k];
            ae += w.x * e.x + w.y * e.y + w.z * e.z + w.w * e.w;
#pragma unroll
            for (int b = 0; b < B_; ++b) {
                float4 q = q4[b][k];
                aq[b] += w.x * q.x + w.y * q.y + w.z * q.z + w.w * q.w;
            }
        }
#pragma unroll
        for (int o = 1; o <= 4; o <<= 1) {
            ae += __shfl_xor_sync(0xffffffffu, ae, o);
#pragma unroll
            for (int b = 0; b < B_; ++b) aq[b] += __shfl_xor_sync(0xffffffffu, aq[b], o);
        }
        if (p == 0) {
            float bias = (dir ? bihb : bihf)[l * G_ + j] + (dir ? bhhb : bhhf)[l * G_ + j];
#pragma unroll
            for (int b = 0; b < B_; ++b) {
                int idx = (ld * 8 + b) * G_ + j;
                g_preq[idx] = aq[b] + bias;
                g_pree[idx] = ae + bias;
            }
        }
    }
    gridbar96();

    // --- 4 recurrence steps ---
    for (int s = 0; s < 4; ++s) {
        if (s > 0) {
            int p = gid & 7, row = gid >> 3;
            int ld = row >> 10, j = row & 1023;
            int dir = ld / 3, l = ld - dir * 3;
            const float4* w4 = (const float4*)((dir ? Whhb : Whhf) + ((size_t)(l * G_ + j)) * H_) + p * 8;
            const float4* hb = (const float4*)g_hst + (ld * 8) * 64 + p * 8;
            float acc[B_];
#pragma unroll
            for (int b = 0; b < B_; ++b) acc[b] = 0.f;
#pragma unroll
            for (int k = 0; k < 8; ++k) {
                float4 w = w4[k];
#pragma unroll
                for (int b = 0; b < B_; ++b) {
                    float4 h = hb[b * 64 + k];
                    acc[b] += w.x * h.x + w.y * h.y + w.z * h.z + w.w * h.w;
                }
            }
#pragma unroll
            for (int o = 1; o <= 4; o <<= 1)
#pragma unroll
                for (int b = 0; b < B_; ++b) acc[b] += __shfl_xor_sync(0xffffffffu, acc[b], o);
            if (p == 0) {
                const float* pre = ((dir == 0) && (s == 3)) ? g_pree : g_preq;
#pragma unroll
                for (int b = 0; b < B_; ++b) {
                    int idx = (ld * 8 + b) * G_ + j;
                    g_gates[idx] = pre[idx] + acc[b];
                }
            }
            gridbar96();
        }
        if (gid < 6 * B_ * H_) {
            int idx = gid;
            int ld = idx >> 11;
            int b  = (idx >> 8) & 7;
            int u  = idx & 255;
            int base2 = (ld * 8 + b) * G_;
            float gi, gf, gg, go, cprev;
            if (s == 0) {
                const float* src = (ld >= 3) ? g_pree : g_preq;   // bwd step0 sees emb[-1]
                gi = src[base2 + u]; gf = src[base2 + 256 + u];
                gg = src[base2 + 512 + u]; go = src[base2 + 768 + u];
                cprev = 0.f;
            } else {
                gi = g_gates[base2 + u]; gf = g_gates[base2 + 256 + u];
                gg = g_gates[base2 + 512 + u]; go = g_gates[base2 + 768 + u];
                cprev = g_cst[idx];
            }
            float c = sigm(gf) * cprev + sigm(gi) * tanhf(gg);
            float h = sigm(go) * tanhf(c);
            g_cst[idx] = c;
            g_hst[idx] = h;
            g_hseq[((ld * 4 + s) * 8 + b) * H_ + u] = h;
        }
        gridbar96();
    }

    // --- logits ---
    {
        const int TOTAL = NREL_ * 9 * 8;   // 28872
        int g = (gid < TOTAL) ? gid : (TOTAL - 1);
        int n = g / 72;
        int rem = g % 72;
        int tl = rem >> 3;
        int p = g & 7;
        int t = tl / 3, l = tl - t * 3;
        const float4* w1 = (const float4*)(linW + (size_t)n * 2 * H_) + p * 8;
        const float4* w2 = w1 + 64;
        const float4* hf = (const float4*)g_hseq + ((l * 4 + t) * 8) * 64 + p * 8;
        const float4* hb = (const float4*)g_hseq + (((3 + l) * 4 + (3 - t)) * 8) * 64 + p * 8;
        float acc[B_];
#pragma unroll
        for (int b = 0; b < B_; ++b) acc[b] = 0.f;
#pragma unroll
        for (int k = 0; k < 8; ++k) {
            float4 wa = w1[k], wb = w2[k];
#pragma unroll
            for (int b = 0; b < B_; ++b) {
                float4 a = hf[b * 64 + k];
                float4 c = hb[b * 64 + k];
                acc[b] += a.x * wa.x + a.y * wa.y + a.z * wa.z + a.w * wa.w
                        + c.x * wb.x + c.y * wb.y + c.z * wb.z + c.w * wb.w;
            }
        }
#pragma unroll
        for (int o = 1; o <= 4; o <<= 1)
#pragma unroll
            for (int b = 0; b < B_; ++b) acc[b] += __shfl_xor_sync(0xffffffffu, acc[b], o);
        if (gid < TOTAL && p == 0) {
            float bb = linb[n];
#pragma unroll
            for (int b = 0; b < B_; ++b)
                g_logits[(t * BL_ + b * 3 + l) * NREL_ + n] = acc[b] + bb;
        }
    }
    gridbar96();

    // --- softmax (72 rows over first 72 lstm blocks) ---
    if (bid < T_ * BL_) {
        const float* lg = g_logits + bid * NREL_;
        float* wout = g_w + bid * NREL_;
        float lmax = -1e30f;
        for (int i = tid; i < NREL_; i += 512) {
            float v = lg[i] * 0.1f;
            s_buf[i] = v;
            lmax = fmaxf(lmax, v);
        }
        s_red[tid] = lmax; __syncthreads();
        for (int o = 256; o > 0; o >>= 1) { if (tid < o) s_red[tid] = fmaxf(s_red[tid], s_red[tid + o]); __syncthreads(); }
        float m = s_red[0];
        __syncthreads();
        float lsum = 0.f;
        for (int i = tid; i < NREL_; i += 512) {
            float ex = expf(s_buf[i] - m);
            s_buf[i] = ex;
            lsum += ex;
        }
        s_red[tid] = lsum; __syncthreads();
        for (int o = 256; o > 0; o >>= 1) { if (tid < o) s_red[tid] += s_red[tid + o]; __syncthreads(); }
        float inv = 1.f / s_red[0];
        for (int i = tid; i < NREL_; i += 512) wout[i] = s_buf[i] * inv;
    }
}

// ---------------- fused hops: NSPL blocks per (b,l), dense state in SMEM ----------------
// t0/t1/select run fully redundantly in all NSPL replicas (deterministic radix
// thresholds); t2 propagate is sliced by e % NSPL; partial state dense-written.
__global__ void __launch_bounds__(HTPB, 1)
hops_kernel(const int* __restrict__ input_x) {
    extern __shared__ float s_state[];              // E_ floats = 200 KB
    __shared__ float    s_wr[NREL_];
    __shared__ unsigned s_fre[FRCAP];
    __shared__ float    s_frv[FRCAP];
    __shared__ int      s_hist[256];
    __shared__ float    s_wred[32];
    __shared__ float    s_nrm;
    __shared__ int      s_frc, s_cand;
    __shared__ unsigned shp, shm;
    __shared__ int      shk;

    const int blk = blockIdx.x;                     // 0..143
    const int bl = blk / NSPL;
    const int jslice = blk - bl * NSPL;
    const int tid = threadIdx.x;
    const int lane = tid & 31, wid = tid >> 5;      // 32 warps
    int* cand = g_cand + (size_t)blk * 4096;
    unsigned* ovf_e = g_fr_ovf_e + (size_t)blk * 4096;
    float* ovf_v = g_fr_ovf_v + (size_t)blk * 4096;
    const int sc = gZ.spill;

    // zero state
    float4* st4 = (float4*)s_state;
    for (int i = tid; i < E_ / 4; i += HTPB) st4[i] = make_float4(0.f, 0.f, 0.f, 0.f);
    if (tid == 0) {
        s_frc = 1; s_cand = 0;
        unsigned e = (unsigned)input_x[bl / 3];
        unsigned ch = (unsigned)min(gZ.cnt_h[e], CAP_);
        unsigned ct = (unsigned)min(gZ.cnt_t[e], CAP_);
        s_fre[0] = e | (ch << 16) | (ct << 23);
        s_frv[0] = 1.f;
    }
    __syncthreads();

    float nrm_prev = 1.f;                           // t=0: x0 used unnormalized
    for (int t = 0; t < T_; ++t) {
        for (int i = tid; i < NREL_; i += HTPB) s_wr[i] = g_w[(t * BL_ + bl) * NREL_ + i];
        __syncthreads();
        const float inv = 1.f / fmaxf(nrm_prev, 1e-7f);
        const int fcnt = s_frc;
        const bool track = (t < T_ - 1);            // t2: no tracking, sliced
        float lsum = 0.f;

        // ---------------- propagate: warp per (entry, half) unit ----------------
        for (int u = wid; u < 2 * fcnt; u += 32) {
            int ent = u >> 1;
            int half = u & 1;                        // 0: head-dir, 1: tail-dir
            unsigned pe; float fv;
            if (ent < FRCAP) { pe = s_fre[ent]; fv = s_frv[ent]; }
            else { pe = ovf_e[ent - FRCAP]; fv = ovf_v[ent - FRCAP]; }
            unsigned e = pe & 0xFFFFu;
            if (!track && (int)(e % (unsigned)NSPL) != jslice) continue;   // hop-2 slice
            int cnt = half ? (int)((pe >> 23) & 0x7Fu) : (int)((pe >> 16) & 0x7Fu);
            const unsigned* row = (half ? g_ell_t : g_ell_h) + (size_t)e * CAP_;
            const int rbase = half ? R_ : 0;
            float v = fv * inv;

            // identity relation (half 0, lane 0)
            {
                bool first = false;
                if (half == 0 && lane == 0) {
                    float m = s_wr[NREL_ - 1] * v;
                    float old = atomicAdd(&s_state[e], m);
                    lsum += m;
                    first = (old == 0.f) && (m > 0.f);
                }
                if (track) {
                    unsigned bm = __ballot_sync(0xffffffffu, first);
                    if (bm && lane == 0 && first) { int p = atomicAdd(&s_cand, 1); cand[p] = (int)e; }
                }
            }

            for (int i0 = 0; i0 < cnt; i0 += 32) {
                int i = i0 + lane;
                bool act = (i < cnt);
                unsigned pk = act ? row[i] : 0u;
                bool first = false;
                if (act) {
                    float m = v * s_wr[(pk >> 16) + rbase];
                    float old = atomicAdd(&s_state[pk & 0xFFFFu], m);
                    lsum += m;
                    first = (old == 0.f) && (m > 0.f);
                }
                if (track) {
                    unsigned bm = __ballot_sync(0xffffffffu, first);
                    if (bm) {
                        int ldr = (int)(__ffs(bm) - 1), base;
                        if (lane == ldr) base = atomicAdd(&s_cand, __popc(bm));
                        base = __shfl_sync(0xffffffffu, base, ldr);
                        if (first) cand[base + __popc(bm & ((1u << lane) - 1u))] = (int)(pk & 0xFFFFu);
                    }
                }
            }

            if (sc) {
                for (int i0 = 0; i0 < sc; i0 += 32) {
                    int i = i0 + lane;
                    bool act = (i < sc) && ((unsigned)g_sp_ent[i] == e);
                    unsigned pk = act ? g_sp_pay[i] : 0u;
                    if (act) act = ((int)(pk >> 31) == half);
                    bool first = false;
                    if (act) {
                        int widx = (int)((pk >> 16) & 0x7FFFu) + rbase;
                        float m = v * s_wr[widx];
                        float old = atomicAdd(&s_state[pk & 0xFFFFu], m);
                        lsum += m;
                        first = (old == 0.f) && (m > 0.f);
                    }
                    if (track) {
                        unsigned bm = __ballot_sync(0xffffffffu, first);
                        if (bm) {
                            int ldr = (int)(__ffs(bm) - 1), base;
                            if (lane == ldr) base = atomicAdd(&s_cand, __popc(bm));
                            base = __shfl_sync(0xffffffffu, base, ldr);
                            if (first) cand[base + __popc(bm & ((1u << lane) - 1u))] = (int)(pk & 0xFFFFu);
                        }
                    }
                }
            }
        }
        // block-reduce lsum -> s_nrm
#pragma unroll
        for (int o = 16; o > 0; o >>= 1) lsum += __shfl_down_sync(0xffffffffu, lsum, o);
        if (lane == 0) s_wred[wid] = lsum;
        __syncthreads();
        if (wid == 0) {
            float a = s_wred[lane];
#pragma unroll
            for (int o = 16; o > 0; o >>= 1) a += __shfl_down_sync(0xffffffffu, a, o);
            if (lane == 0) s_nrm = a;
        }
        __syncthreads();
        const float nrm_out = s_nrm;

        if (t == T_ - 1) {
            // epilogue: partial normalizer + dense partial-state write
            if (tid == 0) atomicAdd(&gZ.nrm2[bl], nrm_out);
            float4* dst = (float4*)(g_part + (size_t)blk * E_);
            for (int i = tid; i < E_ / 4; i += HTPB) dst[i] = st4[i];
        } else {
            const int nnz = s_cand;
            float th = 0.f;
            if (nnz > TOPK_) {
                if (tid == 0) { shp = 0u; shm = 0u; shk = TOPK_; }
                __syncthreads();
                for (int pass = 0; pass < 4; ++pass) {
                    int shift = 24 - 8 * pass;
                    if (tid < 256) s_hist[tid] = 0;
                    __syncthreads();
                    unsigned mask = shm, pref = shp;
                    for (int i0 = 0; i0 < nnz; i0 += HTPB) {
                        int i = i0 + tid;
                        bool act = (i < nnz);
                        unsigned bits = act ? __float_as_uint(s_state[cand[i]]) : 0u;
                        bool ok = act && ((bits & mask) == pref);
                        int bin = (bits >> shift) & 255;
                        unsigned am = __ballot_sync(0xffffffffu, ok);
                        if (ok) {
                            unsigned mm = __match_any_sync(am, bin);
                            if (lane == (int)(__ffs(mm) - 1)) atomicAdd(&s_hist[bin], __popc(mm));
                        }
                    }
                    __syncthreads();
                    if (tid == 0) {
                        int cum = 0, krem = shk, sel = 0, newk = krem;
                        for (int bn = 255; bn >= 0; --bn) {
                            int c = s_hist[bn];
                            if (cum + c >= krem) { sel = bn; newk = krem - cum; break; }
                            cum += c;
                        }
                        shp = pref | ((unsigned)sel << shift);
                        shm = mask | (0xFFu << shift);
                        shk = newk;
                    }
                    __syncthreads();
                }
                th = __uint_as_float(shp);
            }
            __syncthreads();
            if (tid == 0) s_frc = 0;
            __syncthreads();
            // sparse compact (keep v >= th) + count pack + zero consumed entries
            for (int i0 = 0; i0 < nnz; i0 += HTPB) {
                int i = i0 + tid;
                bool act = (i < nnz);
                int e = act ? cand[i] : 0;
                float v = act ? s_state[e] : 0.f;
                bool keep = act && (v >= th) && (v > 0.f);
                unsigned packed = 0;
                if (keep) {
                    unsigned ch = (unsigned)min(gZ.cnt_h[e], CAP_);
                    unsigned ct = (unsigned)min(gZ.cnt_t[e], CAP_);
                    packed = (unsigned)e | (ch << 16) | (ct << 23);
                }
                unsigned bm = __ballot_sync(0xffffffffu, keep);
                if (bm) {
                    int ldr = (int)(__ffs(bm) - 1), base;
                    if (lane == ldr) base = atomicAdd(&s_frc, __popc(bm));
                    base = __shfl_sync(0xffffffffu, base, ldr);
                    if (keep) {
                        int p = base + __popc(bm & ((1u << lane) - 1u));
                        if (p < FRCAP) { s_fre[p] = packed; s_frv[p] = v; }
                        else { ovf_e[p - FRCAP] = packed; ovf_v[p - FRCAP] = v; }
                    }
                }
                if (act) s_state[e] = 0.f;
            }
            __syncthreads();
            if (tid == 0) s_cand = 0;
            nrm_prev = nrm_out;
            __syncthreads();
        }
    }
}

// ---------------- output merge: 48 blocks, dense streaming ----------------
__global__ void __launch_bounds__(HTPB)
out_kernel(float* __restrict__ out) {
    const int b = blockIdx.x / NSPL;
    const int seg = blockIdx.x - b * NSPL;
    __shared__ float s_inv[L_];
    if (threadIdx.x < L_)
        s_inv[threadIdx.x] = 1.f / fmaxf(gZ.nrm2[b * 3 + threadIdx.x], 1e-7f);
    __syncthreads();
    const int CH = (E_ / 4 + NSPL - 1) / NSPL;      // float4 chunks per segment
    int lo = seg * CH, hi = min(lo + CH, E_ / 4);
    float4* ob = (float4*)(out + (size_t)b * E_);
    for (int i = lo + threadIdx.x; i < hi; i += HTPB) {
        float4 acc = make_float4(0.f, 0.f, 0.f, 0.f);
#pragma unroll
        for (int l = 0; l < L_; ++l) {
            float iv = s_inv[l];
#pragma unroll
            for (int j = 0; j < NSPL; ++j) {
                const float4 p = ((const float4*)(g_part + (size_t)((b * 3 + l) * NSPL + j) * E_))[i];
                acc.x += p.x * iv; acc.y += p.y * iv;
                acc.z += p.z * iv; acc.w += p.w * iv;
            }
        }
        ob[i] = acc;
    }
}

// ---------------- launch (single stream) ----------------
extern "C" void kernel_launch(void* const* d_in, const int* in_sizes, int n_in,
                              void* d_out, int out_size) {
    (void)in_sizes; (void)n_in; (void)out_size;
    const int*   input_x = (const int*)d_in[0];
    const int*   input_r = (const int*)d_in[1];
    const int*   e2      = (const int*)d_in[2];
    const int*   t2e     = (const int*)d_in[3];
    const int*   r2      = (const int*)d_in[4];
    const float* emb     = (const float*)d_in[5];

    static bool init = false;
    if (!init) {
        cudaFuncSetAttribute(hops_kernel, cudaFuncAttributeMaxDynamicSharedMemorySize, E_ * 4);
        init = true;
    }

    void* pZ;
    cudaGetSymbolAddress(&pZ, gZ);
    cudaMemsetAsync(pZ, 0, sizeof(Zs), 0);

    // BiLSTM (96 blocks, placed first) + build (489 blocks), overlapped in one launch
    combo_kernel<<<LSTM_BLKS + BUILD_BLKS, 512>>>(
        (const int4*)e2, (const int4*)(t2e + N_), (const int4*)r2, (const int4*)(e2 + 2 * N_),
        input_r, emb,
        (const float*)d_in[6], (const float*)d_in[7], (const float*)d_in[8],
        (const float*)d_in[9], (const float*)d_in[10], (const float*)d_in[11],
        (const float*)d_in[12], (const float*)d_in[13], (const float*)d_in[14],
        (const float*)d_in[15]);

    // fused hops: NSPL replicas per (b,l); t2 sliced by e%NSPL into partial states
    hops_kernel<<<BL_ * NSPL, HTPB, E_ * 4>>>(input_x);

    // merge partials + normalize -> dense output
    out_kernel<<<B_ * NSPL, HTPB>>>((float*)d_out);
}